// round 14
// baseline (speedup 1.0000x reference)
#include <cuda_runtime.h>
#include <cuda_bf16.h>
#include <cstdint>

// Problem constants
#define NN 200000
#define NPAD 200064          // 1563 * 128
#define EE 600000
#define GG 8192
#define HH 128
#define DIN 30

typedef unsigned long long u64;
typedef unsigned int u32;

// ---------------- scratch (device globals; no allocations allowed) ----------
__device__ float g_aggx[(size_t)NPAD * 32];  // aggregated input (Â·X), K padded 32
__device__ __nv_bfloat16 g_w1h[128 * 32],  g_w1l[128 * 32];    // W1^T split
__device__ __nv_bfloat16 g_w2h[128 * 128], g_w2l[128 * 128];   // W2^T split
__device__ __nv_bfloat16 g_w3h[128 * 128], g_w3l[128 * 128];   // W3^T split
__device__ float g_h[(size_t)NPAD * HH];    // h = act @ W
__device__ float g_agg[(size_t)NPAD * HH];  // aggregation / pre-activation buffer
__device__ float g_deg[NN];                 // 1 + in-degree
__device__ float g_cnt[GG];                 // raw batch counts

// ---------------- helpers -----------------------------------------------------
__device__ __forceinline__ u32 smem_u32(const void* p) {
    u32 a;
    asm("{ .reg .u64 t; cvta.to.shared.u64 t, %1; cvt.u32.u64 %0, t; }" : "=r"(a) : "l"(p));
    return a;
}
__device__ __forceinline__ u32 pack2(__nv_bfloat16 a, __nv_bfloat16 b) {
    return (u32)__bfloat16_as_ushort(a) | ((u32)__bfloat16_as_ushort(b) << 16);
}
__device__ __forceinline__ void split8(const float* v, uint4& hi, uint4& lo) {
    __nv_bfloat16 h[8];
    float r[8];
#pragma unroll
    for (int i = 0; i < 8; i++) { h[i] = __float2bfloat16(v[i]); r[i] = v[i] - __bfloat162float(h[i]); }
    hi.x = pack2(h[0], h[1]); hi.y = pack2(h[2], h[3]);
    hi.z = pack2(h[4], h[5]); hi.w = pack2(h[6], h[7]);
    lo.x = pack2(__float2bfloat16(r[0]), __float2bfloat16(r[1]));
    lo.y = pack2(__float2bfloat16(r[2]), __float2bfloat16(r[3]));
    lo.z = pack2(__float2bfloat16(r[4]), __float2bfloat16(r[5]));
    lo.w = pack2(__float2bfloat16(r[6]), __float2bfloat16(r[7]));
}
__device__ __forceinline__ void mma16816(float* c, const u32* a, const u32* b) {
    asm volatile(
        "mma.sync.aligned.m16n8k16.row.col.f32.bf16.bf16.f32 "
        "{%0,%1,%2,%3}, {%4,%5,%6,%7}, {%8,%9}, {%0,%1,%2,%3};"
        : "+f"(c[0]), "+f"(c[1]), "+f"(c[2]), "+f"(c[3])
        : "r"(a[0]), "r"(a[1]), "r"(a[2]), "r"(a[3]), "r"(b[0]), "r"(b[1]));
}
__device__ __forceinline__ void ldsm4(u32* r, u32 addr) {
    asm volatile("ldmatrix.sync.aligned.m8n8.x4.shared.b16 {%0,%1,%2,%3}, [%4];"
                 : "=r"(r[0]), "=r"(r[1]), "=r"(r[2]), "=r"(r[3]) : "r"(addr));
}
__device__ __forceinline__ void redv4(float* p, float4 m) {
    asm volatile("red.global.add.v4.f32 [%0], {%1, %2, %3, %4};"
                 :: "l"(p), "f"(m.x), "f"(m.y), "f"(m.z), "f"(m.w)
                 : "memory");
}

// ---------------- setup: zero out/deg/cnt + split all weights ----------------
__global__ void init_kernel(float* __restrict__ out,
                            const float* __restrict__ W1,
                            const float* __restrict__ W2,
                            const float* __restrict__ W3) {
    int idx = blockIdx.x * blockDim.x + threadIdx.x;
    if (idx < GG * HH) out[idx] = 0.0f;
    if (idx < NN) g_deg[idx] = 1.0f;           // self-loop
    if (idx < GG) g_cnt[idx] = 0.0f;
    if (idx < 128 * 32) {
        int c = idx >> 5, k = idx & 31;
        float v = (k < DIN) ? W1[(size_t)k * HH + c] : 0.0f;
        __nv_bfloat16 h = __float2bfloat16(v);
        g_w1h[idx] = h;
        g_w1l[idx] = __float2bfloat16(v - __bfloat162float(h));
    }
    if (idx < 128 * 128) {
        int c = idx >> 7, k = idx & 127;
        float v2 = W2[(size_t)k * HH + c];
        __nv_bfloat16 h2 = __float2bfloat16(v2);
        g_w2h[idx] = h2;
        g_w2l[idx] = __float2bfloat16(v2 - __bfloat162float(h2));
        float v3 = W3[(size_t)k * HH + c];
        __nv_bfloat16 h3 = __float2bfloat16(v3);
        g_w3h[idx] = h3;
        g_w3l[idx] = __float2bfloat16(v3 - __bfloat162float(h3));
    }
}

__global__ void count_kernel(const int* __restrict__ dst, const int* __restrict__ batch_idx) {
    int idx = blockIdx.x * blockDim.x + threadIdx.x;
    if (idx < EE) atomicAdd(&g_deg[dst[idx]], 1.0f);
    if (idx < NN) atomicAdd(&g_cnt[batch_idx[idx]], 1.0f);
}

// seed aggx with self-loop term x/deg (coalesced)
__global__ void aggxinit_kernel(const float* __restrict__ x) {
    int idx = blockIdx.x * blockDim.x + threadIdx.x;   // over NPAD*8
    if (idx >= NPAD * 8) return;
    int n = idx >> 3;
    int k = (idx & 7) * 4;
    float4 v = make_float4(0.f, 0.f, 0.f, 0.f);
    if (n < NN) {
        float d2 = __frcp_rn(g_deg[n]);
        if (k + 0 < DIN) v.x = x[(size_t)n * DIN + k + 0] * d2;
        if (k + 1 < DIN) v.y = x[(size_t)n * DIN + k + 1] * d2;
        if (k + 2 < DIN) v.z = x[(size_t)n * DIN + k + 2] * d2;
        if (k + 3 < DIN) v.w = x[(size_t)n * DIN + k + 3] * d2;
    }
    *(float4*)&g_aggx[(size_t)n * 32 + k] = v;
}

// 30-dim edge scatter on raw x, ILP-2 (unchanged from best)
__global__ void __launch_bounds__(256) scatterx_kernel(const float* __restrict__ x,
                                                       const int* __restrict__ src,
                                                       const int* __restrict__ dst) {
    int grp = blockIdx.x * 32 + (threadIdx.x >> 3);
    int e0 = grp * 2;
    if (e0 >= EE) return;
    int l = threadIdx.x & 7;
    int s0 = __ldg(&src[e0]),     d0 = __ldg(&dst[e0]);
    int s1 = __ldg(&src[e0 + 1]), d1 = __ldg(&dst[e0 + 1]);
    float w0 = rsqrtf(g_deg[s0] * g_deg[d0]);
    float w1 = rsqrtf(g_deg[s1] * g_deg[d1]);
    float v0[4], v1[4];
#pragma unroll
    for (int j = 0; j < 4; j++) {
        int k = l * 4 + j;
        v0[j] = (k < DIN) ? __ldg(&x[(size_t)s0 * DIN + k]) : 0.f;
        v1[j] = (k < DIN) ? __ldg(&x[(size_t)s1 * DIN + k]) : 0.f;
    }
    redv4(&g_aggx[(size_t)d0 * 32 + l * 4],
          make_float4(v0[0] * w0, v0[1] * w0, v0[2] * w0, v0[3] * w0));
    redv4(&g_aggx[(size_t)d1 * 32 + l * 4],
          make_float4(v1[0] * w1, v1[1] * w1, v1[2] * w1, v1[3] * w1));
}

// ---------------- tensor-core GEMM (identical to best) ----------------------
template <int KT, int RELU, int WAGG>
__global__ void __launch_bounds__(256) gemm_mma(
    const float* __restrict__ inf, const float* __restrict__ bias,
    const __nv_bfloat16* __restrict__ wh, const __nv_bfloat16* __restrict__ wl,
    float* __restrict__ hout, float* __restrict__ agg)
{
    constexpr int KC = (KT < 64) ? KT : 64;
    constexpr u32 SPB = (KC + 8) * 2;
    constexpr u32 TILEB = 128 * SPB;
    constexpr int UNITS = 128 * (KC / 8);

    extern __shared__ char smem[];
    const u32 sb = smem_u32(smem);
    char* Ah = smem;
    char* Al = smem + TILEB;
    char* Whs = smem + 2 * TILEB;
    char* Wls = smem + 3 * TILEB;

    const int tid   = threadIdx.x;
    const int w     = tid >> 5;
    const int lane  = tid & 31;
    const int mrow  = (w & 3) * 32;
    const int ncol  = (w >> 2) * 64;
    const int node0 = blockIdx.x * 128;

    const u32 aAh = sb + (u32)(mrow + (lane & 15)) * SPB + (u32)((lane >> 4) * 16);
    const u32 bWh = sb + 2 * TILEB
                  + (u32)(ncol + (lane & 7) + ((lane >> 4) << 3)) * SPB
                  + (u32)(((lane >> 3) & 1) * 16);

    float acc[2][8][4];
#pragma unroll
    for (int mt = 0; mt < 2; mt++)
#pragma unroll
        for (int nt = 0; nt < 8; nt++)
#pragma unroll
            for (int i = 0; i < 4; i++) acc[mt][nt][i] = 0.f;

    for (int c = 0; c < KT / KC; c++) {
        const int k0 = c * KC;
        if (c) __syncthreads();
        for (int u = tid; u < UNITS; u += 256) {
            int row = u / (KC / 8);
            int cu  = u % (KC / 8);
            uint4 vh = *(const uint4*)&wh[(size_t)row * KT + k0 + cu * 8];
            uint4 vl = *(const uint4*)&wl[(size_t)row * KT + k0 + cu * 8];
            *(uint4*)(Whs + row * SPB + cu * 16) = vh;
            *(uint4*)(Wls + row * SPB + cu * 16) = vl;
        }
        for (int u = tid; u < UNITS; u += 256) {
            int row = u / (KC / 8);
            int cu  = u % (KC / 8);
            const float* s = inf + (size_t)(node0 + row) * KT + k0 + cu * 8;
            float4 a0 = *(const float4*)s;
            float4 a1 = *(const float4*)(s + 4);
            float v[8];
            if (RELU) {
                float4 b0 = *(const float4*)&bias[k0 + cu * 8];
                float4 b1 = *(const float4*)&bias[k0 + cu * 8 + 4];
                v[0] = fmaxf(a0.x + b0.x, 0.f); v[1] = fmaxf(a0.y + b0.y, 0.f);
                v[2] = fmaxf(a0.z + b0.z, 0.f); v[3] = fmaxf(a0.w + b0.w, 0.f);
                v[4] = fmaxf(a1.x + b1.x, 0.f); v[5] = fmaxf(a1.y + b1.y, 0.f);
                v[6] = fmaxf(a1.z + b1.z, 0.f); v[7] = fmaxf(a1.w + b1.w, 0.f);
            } else {
                v[0] = a0.x; v[1] = a0.y; v[2] = a0.z; v[3] = a0.w;
                v[4] = a1.x; v[5] = a1.y; v[6] = a1.z; v[7] = a1.w;
            }
            uint4 vh, vl;
            split8(v, vh, vl);
            *(uint4*)(Ah + row * SPB + cu * 16) = vh;
            *(uint4*)(Al + row * SPB + cu * 16) = vl;
        }
        __syncthreads();

#pragma unroll
        for (int ks = 0; ks < KC / 16; ks++) {
            const u32 koff = (u32)(ks * 32);
            u32 ah0[4], ah1[4], al0[4], al1[4];
            ldsm4(ah0, aAh + koff);
            ldsm4(ah1, aAh + 16 * SPB + koff);
            ldsm4(al0, aAh + TILEB + koff);
            ldsm4(al1, aAh + TILEB + 16 * SPB + koff);
#pragma unroll
            for (int np = 0; np < 4; np++) {
                const u32 bo = (u32)(np * 16) * SPB + koff;
                u32 bh4[4], bl4[4];
                ldsm4(bh4, bWh + bo);
                ldsm4(bl4, bWh + TILEB + bo);
                const int nt0 = np * 2, nt1 = np * 2 + 1;
                mma16816(acc[0][nt0], ah0, bh4);
                mma16816(acc[1][nt0], ah1, bh4);
                mma16816(acc[0][nt1], ah0, bh4 + 2);
                mma16816(acc[1][nt1], ah1, bh4 + 2);
                mma16816(acc[0][nt0], ah0, bl4);
                mma16816(acc[1][nt0], ah1, bl4);
                mma16816(acc[0][nt1], ah0, bl4 + 2);
                mma16816(acc[1][nt1], ah1, bl4 + 2);
                mma16816(acc[0][nt0], al0, bh4);
                mma16816(acc[1][nt0], al1, bh4);
                mma16816(acc[0][nt1], al0, bh4 + 2);
                mma16816(acc[1][nt1], al1, bh4 + 2);
            }
        }
    }

#pragma unroll
    for (int mt = 0; mt < 2; mt++) {
        int r0 = node0 + mrow + mt * 16 + (lane >> 2);
        int r1 = r0 + 8;
        float d20 = 0.f, d21 = 0.f;
        if (WAGG) {
            if (r0 < NN) d20 = __frcp_rn(g_deg[r0]);
            if (r1 < NN) d21 = __frcp_rn(g_deg[r1]);
        }
#pragma unroll
        for (int nt = 0; nt < 8; nt++) {
            int cc = ncol + nt * 8 + (lane & 3) * 2;
            float2 h0 = make_float2(acc[mt][nt][0], acc[mt][nt][1]);
            float2 h1 = make_float2(acc[mt][nt][2], acc[mt][nt][3]);
            *(float2*)&hout[(size_t)r0 * HH + cc] = h0;
            *(float2*)&hout[(size_t)r1 * HH + cc] = h1;
            if (WAGG) {
                *(float2*)&agg[(size_t)r0 * HH + cc] = make_float2(h0.x * d20, h0.y * d20);
                *(float2*)&agg[(size_t)r1 * HH + cc] = make_float2(h1.x * d21, h1.y * d21);
            }
        }
    }
}

// ---------------- 128-dim scatter, TWO-PASS over feature halves -------------
// Pass C0 touches only h[:, C0:C0+64) and agg[:, C0:C0+64): 51+51 MB working
// set fits L2. 16-lane groups, 4 edges per group (ILP-4). (R11 best config.)
template <int C0>
__global__ void __launch_bounds__(256) scatter_half_kernel(const int* __restrict__ src,
                                                           const int* __restrict__ dst) {
    int grp = blockIdx.x * 16 + (threadIdx.x >> 4);
    int e0 = grp * 4;
    if (e0 >= EE) return;              // EE % 4 == 0, so e0..e0+3 all valid
    int l = threadIdx.x & 15;
    int s[4], d[4];
#pragma unroll
    for (int i = 0; i < 4; i++) {
        s[i] = __ldg(&src[e0 + i]);
        d[i] = __ldg(&dst[e0 + i]);
    }
    float wt[4];
#pragma unroll
    for (int i = 0; i < 4; i++)
        wt[i] = rsqrtf(g_deg[s[i]] * g_deg[d[i]]);
    float4 v[4];
#pragma unroll
    for (int i = 0; i < 4; i++)
        v[i] = *(const float4*)&g_h[(size_t)s[i] * HH + C0 + l * 4];
#pragma unroll
    for (int i = 0; i < 4; i++)
        redv4(&g_agg[(size_t)d[i] * HH + C0 + l * 4],
              make_float4(v[i].x * wt[i], v[i].y * wt[i], v[i].z * wt[i], v[i].w * wt[i]));
}

// ---------------- final pool: run-batched over sorted batch_idx -------------
// Warp owns a 32-node strip; accumulates relu(agg+b) in registers while the
// graph id is unchanged (batch_idx sorted), flushing one red.v4 per run.
__global__ void __launch_bounds__(256) pool_kernel(const float* __restrict__ bias,
                                                   const int* __restrict__ batch_idx,
                                                   float* __restrict__ out) {
    int warp = blockIdx.x * 8 + (threadIdx.x >> 5);
    int n0 = warp * 32;
    if (n0 >= NN) return;
    int lane = threadIdx.x & 31;
    int c4 = lane * 4;
    float4 b = *(const float4*)&bias[c4];
    float4 acc = make_float4(0.f, 0.f, 0.f, 0.f);
    int gprev = __ldg(&batch_idx[n0]);
    int nend = (n0 + 32 < NN) ? n0 + 32 : NN;
    for (int n = n0; n < nend; n++) {
        int g = __ldg(&batch_idx[n]);
        if (g != gprev) {
            float w = __frcp_rn(fmaxf(g_cnt[gprev], 1.0f));
            redv4(&out[(size_t)gprev * HH + c4],
                  make_float4(acc.x * w, acc.y * w, acc.z * w, acc.w * w));
            acc = make_float4(0.f, 0.f, 0.f, 0.f);
            gprev = g;
        }
        float4 a = *(const float4*)&g_agg[(size_t)n * HH + c4];
        acc.x += fmaxf(a.x + b.x, 0.f);
        acc.y += fmaxf(a.y + b.y, 0.f);
        acc.z += fmaxf(a.z + b.z, 0.f);
        acc.w += fmaxf(a.w + b.w, 0.f);
    }
    float w = __frcp_rn(fmaxf(g_cnt[gprev], 1.0f));
    redv4(&out[(size_t)gprev * HH + c4],
          make_float4(acc.x * w, acc.y * w, acc.z * w, acc.w * w));
}

// ---------------- launch ------------------------------------------------------
extern "C" void kernel_launch(void* const* d_in, const int* in_sizes, int n_in,
                              void* d_out, int out_size) {
    const float* x         = (const float*)d_in[0];
    const int*   edge      = (const int*)d_in[1];     // [2, E]
    const int*   batch_idx = (const int*)d_in[2];
    const float* W1        = (const float*)d_in[3];
    const float* b1        = (const float*)d_in[4];
    const float* W2        = (const float*)d_in[5];
    const float* b2        = (const float*)d_in[6];
    const float* W3        = (const float*)d_in[7];
    const float* b3        = (const float*)d_in[8];
    float* out = (float*)d_out;

    const int* src = edge;
    const int* dst = edge + EE;

    float *hptr, *aggptr, *aggx;
    __nv_bfloat16 *w1h, *w1l, *w2h, *w2l, *w3h, *w3l;
    cudaGetSymbolAddress((void**)&hptr,   g_h);
    cudaGetSymbolAddress((void**)&aggptr, g_agg);
    cudaGetSymbolAddress((void**)&aggx,   g_aggx);
    cudaGetSymbolAddress((void**)&w1h, g_w1h);
    cudaGetSymbolAddress((void**)&w1l, g_w1l);
    cudaGetSymbolAddress((void**)&w2h, g_w2h);
    cudaGetSymbolAddress((void**)&w2l, g_w2l);
    cudaGetSymbolAddress((void**)&w3h, g_w3h);
    cudaGetSymbolAddress((void**)&w3l, g_w3l);

    const int SMEM_L1 = 4 * 128 * (32 + 8) * 2;   // 40960
    const int SMEM_L2 = 4 * 128 * (64 + 8) * 2;   // 73728
    cudaFuncSetAttribute(gemm_mma<32, 0, 0>,  cudaFuncAttributeMaxDynamicSharedMemorySize, SMEM_L1);
    cudaFuncSetAttribute(gemm_mma<128, 1, 1>, cudaFuncAttributeMaxDynamicSharedMemorySize, SMEM_L2);

    const int T = 256;
    const int gemm_grid = NPAD / 128;             // 1563
    const int half_grid = (EE / 4 + 15) / 16;     // 9375 (16 groups x 4 edges)
    const int scx_grid  = (EE / 2 + 31) / 32;     // 9375
    const int pool_grid = (NN / 32 + 7) / 8;      // 782

    init_kernel<<<(GG * HH + T - 1) / T, T>>>(out, W1, W2, W3);
    count_kernel<<<(EE + T - 1) / T, T>>>(dst, batch_idx);
    aggxinit_kernel<<<(NPAD * 8 + T - 1) / T, T>>>(x);
    scatterx_kernel<<<scx_grid, T>>>(x, src, dst);

    // layer 1: agg1 = (Â·X) @ W1  (no post-GEMM scatter)
    gemm_mma<32, 0, 0><<<gemm_grid, T, SMEM_L1>>>(aggx, nullptr, w1h, w1l, aggptr, nullptr);

    // layer 2
    gemm_mma<128, 1, 1><<<gemm_grid, T, SMEM_L2>>>(aggptr, b1, w2h, w2l, hptr, aggptr);
    scatter_half_kernel<0><<<half_grid, T>>>(src, dst);
    scatter_half_kernel<64><<<half_grid, T>>>(src, dst);

    // layer 3
    gemm_mma<128, 1, 1><<<gemm_grid, T, SMEM_L2>>>(aggptr, b2, w3h, w3l, hptr, aggptr);
    scatter_half_kernel<0><<<half_grid, T>>>(src, dst);
    scatter_half_kernel<64><<<half_grid, T>>>(src, dst);

    // final: run-batched relu + b3 + mean-pool
    pool_kernel<<<pool_grid, T>>>(b3, batch_idx, out);
}

// round 15
// speedup vs baseline: 1.3990x; 1.3990x over previous
#include <cuda_runtime.h>
#include <cuda_bf16.h>
#include <cstdint>

// Problem constants
#define NN 200000
#define NPAD 200064          // 1563 * 128
#define EE 600000
#define GG 8192
#define HH 128
#define DIN 30

typedef unsigned long long u64;
typedef unsigned int u32;

// ---------------- scratch (device globals; no allocations allowed) ----------
__device__ float g_aggx[(size_t)NPAD * 32];  // aggregated input (Â·X), K padded 32
__device__ __nv_bfloat16 g_w1h[128 * 32],  g_w1l[128 * 32];    // W1^T split
__device__ __nv_bfloat16 g_w2h[128 * 128], g_w2l[128 * 128];   // W2^T split
__device__ __nv_bfloat16 g_w3h[128 * 128], g_w3l[128 * 128];   // W3^T split
__device__ float g_h[(size_t)NPAD * HH];    // h = act @ W
__device__ float g_agg[(size_t)NPAD * HH];  // aggregation / pre-activation buffer
__device__ float g_deg[NN];                 // 1 + in-degree
__device__ float g_cnt[GG];                 // raw batch counts

// ---------------- helpers -----------------------------------------------------
__device__ __forceinline__ u32 smem_u32(const void* p) {
    u32 a;
    asm("{ .reg .u64 t; cvta.to.shared.u64 t, %1; cvt.u32.u64 %0, t; }" : "=r"(a) : "l"(p));
    return a;
}
__device__ __forceinline__ u32 pack2(__nv_bfloat16 a, __nv_bfloat16 b) {
    return (u32)__bfloat16_as_ushort(a) | ((u32)__bfloat16_as_ushort(b) << 16);
}
__device__ __forceinline__ void split8(const float* v, uint4& hi, uint4& lo) {
    __nv_bfloat16 h[8];
    float r[8];
#pragma unroll
    for (int i = 0; i < 8; i++) { h[i] = __float2bfloat16(v[i]); r[i] = v[i] - __bfloat162float(h[i]); }
    hi.x = pack2(h[0], h[1]); hi.y = pack2(h[2], h[3]);
    hi.z = pack2(h[4], h[5]); hi.w = pack2(h[6], h[7]);
    lo.x = pack2(__float2bfloat16(r[0]), __float2bfloat16(r[1]));
    lo.y = pack2(__float2bfloat16(r[2]), __float2bfloat16(r[3]));
    lo.z = pack2(__float2bfloat16(r[4]), __float2bfloat16(r[5]));
    lo.w = pack2(__float2bfloat16(r[6]), __float2bfloat16(r[7]));
}
__device__ __forceinline__ void mma16816(float* c, const u32* a, const u32* b) {
    asm volatile(
        "mma.sync.aligned.m16n8k16.row.col.f32.bf16.bf16.f32 "
        "{%0,%1,%2,%3}, {%4,%5,%6,%7}, {%8,%9}, {%0,%1,%2,%3};"
        : "+f"(c[0]), "+f"(c[1]), "+f"(c[2]), "+f"(c[3])
        : "r"(a[0]), "r"(a[1]), "r"(a[2]), "r"(a[3]), "r"(b[0]), "r"(b[1]));
}
__device__ __forceinline__ void ldsm4(u32* r, u32 addr) {
    asm volatile("ldmatrix.sync.aligned.m8n8.x4.shared.b16 {%0,%1,%2,%3}, [%4];"
                 : "=r"(r[0]), "=r"(r[1]), "=r"(r[2]), "=r"(r[3]) : "r"(addr));
}
__device__ __forceinline__ void redv4(float* p, float4 m) {
    asm volatile("red.global.add.v4.f32 [%0], {%1, %2, %3, %4};"
                 :: "l"(p), "f"(m.x), "f"(m.y), "f"(m.z), "f"(m.w)
                 : "memory");
}

// ---------------- setup: zero out/deg/cnt + split all weights ----------------
__global__ void init_kernel(float* __restrict__ out,
                            const float* __restrict__ W1,
                            const float* __restrict__ W2,
                            const float* __restrict__ W3) {
    int idx = blockIdx.x * blockDim.x + threadIdx.x;
    if (idx < GG * HH) out[idx] = 0.0f;
    if (idx < NN) g_deg[idx] = 1.0f;           // self-loop
    if (idx < GG) g_cnt[idx] = 0.0f;
    if (idx < 128 * 32) {
        int c = idx >> 5, k = idx & 31;
        float v = (k < DIN) ? W1[(size_t)k * HH + c] : 0.0f;
        __nv_bfloat16 h = __float2bfloat16(v);
        g_w1h[idx] = h;
        g_w1l[idx] = __float2bfloat16(v - __bfloat162float(h));
    }
    if (idx < 128 * 128) {
        int c = idx >> 7, k = idx & 127;
        float v2 = W2[(size_t)k * HH + c];
        __nv_bfloat16 h2 = __float2bfloat16(v2);
        g_w2h[idx] = h2;
        g_w2l[idx] = __float2bfloat16(v2 - __bfloat162float(h2));
        float v3 = W3[(size_t)k * HH + c];
        __nv_bfloat16 h3 = __float2bfloat16(v3);
        g_w3h[idx] = h3;
        g_w3l[idx] = __float2bfloat16(v3 - __bfloat162float(h3));
    }
}

__global__ void count_kernel(const int* __restrict__ dst, const int* __restrict__ batch_idx) {
    int idx = blockIdx.x * blockDim.x + threadIdx.x;
    if (idx < EE) atomicAdd(&g_deg[dst[idx]], 1.0f);
    if (idx < NN) atomicAdd(&g_cnt[batch_idx[idx]], 1.0f);
}

// seed aggx with self-loop term x/deg (coalesced)
__global__ void aggxinit_kernel(const float* __restrict__ x) {
    int idx = blockIdx.x * blockDim.x + threadIdx.x;   // over NPAD*8
    if (idx >= NPAD * 8) return;
    int n = idx >> 3;
    int k = (idx & 7) * 4;
    float4 v = make_float4(0.f, 0.f, 0.f, 0.f);
    if (n < NN) {
        float d2 = __frcp_rn(g_deg[n]);
        if (k + 0 < DIN) v.x = x[(size_t)n * DIN + k + 0] * d2;
        if (k + 1 < DIN) v.y = x[(size_t)n * DIN + k + 1] * d2;
        if (k + 2 < DIN) v.z = x[(size_t)n * DIN + k + 2] * d2;
        if (k + 3 < DIN) v.w = x[(size_t)n * DIN + k + 3] * d2;
    }
    *(float4*)&g_aggx[(size_t)n * 32 + k] = v;
}

// 30-dim edge scatter on raw x, ILP-2 (unchanged from best)
__global__ void __launch_bounds__(256) scatterx_kernel(const float* __restrict__ x,
                                                       const int* __restrict__ src,
                                                       const int* __restrict__ dst) {
    int grp = blockIdx.x * 32 + (threadIdx.x >> 3);
    int e0 = grp * 2;
    if (e0 >= EE) return;
    int l = threadIdx.x & 7;
    int s0 = __ldg(&src[e0]),     d0 = __ldg(&dst[e0]);
    int s1 = __ldg(&src[e0 + 1]), d1 = __ldg(&dst[e0 + 1]);
    float w0 = rsqrtf(g_deg[s0] * g_deg[d0]);
    float w1 = rsqrtf(g_deg[s1] * g_deg[d1]);
    float v0[4], v1[4];
#pragma unroll
    for (int j = 0; j < 4; j++) {
        int k = l * 4 + j;
        v0[j] = (k < DIN) ? __ldg(&x[(size_t)s0 * DIN + k]) : 0.f;
        v1[j] = (k < DIN) ? __ldg(&x[(size_t)s1 * DIN + k]) : 0.f;
    }
    redv4(&g_aggx[(size_t)d0 * 32 + l * 4],
          make_float4(v0[0] * w0, v0[1] * w0, v0[2] * w0, v0[3] * w0));
    redv4(&g_aggx[(size_t)d1 * 32 + l * 4],
          make_float4(v1[0] * w1, v1[1] * w1, v1[2] * w1, v1[3] * w1));
}

// ---------------- tensor-core GEMM (identical to best) ----------------------
template <int KT, int RELU, int WAGG>
__global__ void __launch_bounds__(256) gemm_mma(
    const float* __restrict__ inf, const float* __restrict__ bias,
    const __nv_bfloat16* __restrict__ wh, const __nv_bfloat16* __restrict__ wl,
    float* __restrict__ hout, float* __restrict__ agg)
{
    constexpr int KC = (KT < 64) ? KT : 64;
    constexpr u32 SPB = (KC + 8) * 2;
    constexpr u32 TILEB = 128 * SPB;
    constexpr int UNITS = 128 * (KC / 8);

    extern __shared__ char smem[];
    const u32 sb = smem_u32(smem);
    char* Ah = smem;
    char* Al = smem + TILEB;
    char* Whs = smem + 2 * TILEB;
    char* Wls = smem + 3 * TILEB;

    const int tid   = threadIdx.x;
    const int w     = tid >> 5;
    const int lane  = tid & 31;
    const int mrow  = (w & 3) * 32;
    const int ncol  = (w >> 2) * 64;
    const int node0 = blockIdx.x * 128;

    const u32 aAh = sb + (u32)(mrow + (lane & 15)) * SPB + (u32)((lane >> 4) * 16);
    const u32 bWh = sb + 2 * TILEB
                  + (u32)(ncol + (lane & 7) + ((lane >> 4) << 3)) * SPB
                  + (u32)(((lane >> 3) & 1) * 16);

    float acc[2][8][4];
#pragma unroll
    for (int mt = 0; mt < 2; mt++)
#pragma unroll
        for (int nt = 0; nt < 8; nt++)
#pragma unroll
            for (int i = 0; i < 4; i++) acc[mt][nt][i] = 0.f;

    for (int c = 0; c < KT / KC; c++) {
        const int k0 = c * KC;
        if (c) __syncthreads();
        for (int u = tid; u < UNITS; u += 256) {
            int row = u / (KC / 8);
            int cu  = u % (KC / 8);
            uint4 vh = *(const uint4*)&wh[(size_t)row * KT + k0 + cu * 8];
            uint4 vl = *(const uint4*)&wl[(size_t)row * KT + k0 + cu * 8];
            *(uint4*)(Whs + row * SPB + cu * 16) = vh;
            *(uint4*)(Wls + row * SPB + cu * 16) = vl;
        }
        for (int u = tid; u < UNITS; u += 256) {
            int row = u / (KC / 8);
            int cu  = u % (KC / 8);
            const float* s = inf + (size_t)(node0 + row) * KT + k0 + cu * 8;
            float4 a0 = *(const float4*)s;
            float4 a1 = *(const float4*)(s + 4);
            float v[8];
            if (RELU) {
                float4 b0 = *(const float4*)&bias[k0 + cu * 8];
                float4 b1 = *(const float4*)&bias[k0 + cu * 8 + 4];
                v[0] = fmaxf(a0.x + b0.x, 0.f); v[1] = fmaxf(a0.y + b0.y, 0.f);
                v[2] = fmaxf(a0.z + b0.z, 0.f); v[3] = fmaxf(a0.w + b0.w, 0.f);
                v[4] = fmaxf(a1.x + b1.x, 0.f); v[5] = fmaxf(a1.y + b1.y, 0.f);
                v[6] = fmaxf(a1.z + b1.z, 0.f); v[7] = fmaxf(a1.w + b1.w, 0.f);
            } else {
                v[0] = a0.x; v[1] = a0.y; v[2] = a0.z; v[3] = a0.w;
                v[4] = a1.x; v[5] = a1.y; v[6] = a1.z; v[7] = a1.w;
            }
            uint4 vh, vl;
            split8(v, vh, vl);
            *(uint4*)(Ah + row * SPB + cu * 16) = vh;
            *(uint4*)(Al + row * SPB + cu * 16) = vl;
        }
        __syncthreads();

#pragma unroll
        for (int ks = 0; ks < KC / 16; ks++) {
            const u32 koff = (u32)(ks * 32);
            u32 ah0[4], ah1[4], al0[4], al1[4];
            ldsm4(ah0, aAh + koff);
            ldsm4(ah1, aAh + 16 * SPB + koff);
            ldsm4(al0, aAh + TILEB + koff);
            ldsm4(al1, aAh + TILEB + 16 * SPB + koff);
#pragma unroll
            for (int np = 0; np < 4; np++) {
                const u32 bo = (u32)(np * 16) * SPB + koff;
                u32 bh4[4], bl4[4];
                ldsm4(bh4, bWh + bo);
                ldsm4(bl4, bWh + TILEB + bo);
                const int nt0 = np * 2, nt1 = np * 2 + 1;
                mma16816(acc[0][nt0], ah0, bh4);
                mma16816(acc[1][nt0], ah1, bh4);
                mma16816(acc[0][nt1], ah0, bh4 + 2);
                mma16816(acc[1][nt1], ah1, bh4 + 2);
                mma16816(acc[0][nt0], ah0, bl4);
                mma16816(acc[1][nt0], ah1, bl4);
                mma16816(acc[0][nt1], ah0, bl4 + 2);
                mma16816(acc[1][nt1], ah1, bl4 + 2);
                mma16816(acc[0][nt0], al0, bh4);
                mma16816(acc[1][nt0], al1, bh4);
                mma16816(acc[0][nt1], al0, bh4 + 2);
                mma16816(acc[1][nt1], al1, bh4 + 2);
            }
        }
    }

#pragma unroll
    for (int mt = 0; mt < 2; mt++) {
        int r0 = node0 + mrow + mt * 16 + (lane >> 2);
        int r1 = r0 + 8;
        float d20 = 0.f, d21 = 0.f;
        if (WAGG) {
            if (r0 < NN) d20 = __frcp_rn(g_deg[r0]);
            if (r1 < NN) d21 = __frcp_rn(g_deg[r1]);
        }
#pragma unroll
        for (int nt = 0; nt < 8; nt++) {
            int cc = ncol + nt * 8 + (lane & 3) * 2;
            float2 h0 = make_float2(acc[mt][nt][0], acc[mt][nt][1]);
            float2 h1 = make_float2(acc[mt][nt][2], acc[mt][nt][3]);
            *(float2*)&hout[(size_t)r0 * HH + cc] = h0;
            *(float2*)&hout[(size_t)r1 * HH + cc] = h1;
            if (WAGG) {
                *(float2*)&agg[(size_t)r0 * HH + cc] = make_float2(h0.x * d20, h0.y * d20);
                *(float2*)&agg[(size_t)r1 * HH + cc] = make_float2(h1.x * d21, h1.y * d21);
            }
        }
    }
}

// ---------------- 128-dim scatter, TWO-PASS over feature halves -------------
// Pass C0 touches only h[:, C0:C0+64) and agg[:, C0:C0+64): 51+51 MB working
// set fits L2. 16-lane groups, 4 edges per group (ILP-4). (R11 best config.)
template <int C0>
__global__ void __launch_bounds__(256) scatter_half_kernel(const int* __restrict__ src,
                                                           const int* __restrict__ dst) {
    int grp = blockIdx.x * 16 + (threadIdx.x >> 4);
    int e0 = grp * 4;
    if (e0 >= EE) return;              // EE % 4 == 0, so e0..e0+3 all valid
    int l = threadIdx.x & 15;
    int s[4], d[4];
#pragma unroll
    for (int i = 0; i < 4; i++) {
        s[i] = __ldg(&src[e0 + i]);
        d[i] = __ldg(&dst[e0 + i]);
    }
    float wt[4];
#pragma unroll
    for (int i = 0; i < 4; i++)
        wt[i] = rsqrtf(g_deg[s[i]] * g_deg[d[i]]);
    float4 v[4];
#pragma unroll
    for (int i = 0; i < 4; i++)
        v[i] = *(const float4*)&g_h[(size_t)s[i] * HH + C0 + l * 4];
#pragma unroll
    for (int i = 0; i < 4; i++)
        redv4(&g_agg[(size_t)d[i] * HH + C0 + l * 4],
              make_float4(v[i].x * wt[i], v[i].y * wt[i], v[i].z * wt[i], v[i].w * wt[i]));
}

// ---------------- final pool: run-batched over sorted batch_idx -------------
// Warp owns a 32-node strip; accumulates relu(agg+b) in registers while the
// graph id is unchanged (batch_idx sorted), flushing one red.v4 per run.
__global__ void __launch_bounds__(256) pool_kernel(const float* __restrict__ bias,
                                                   const int* __restrict__ batch_idx,
                                                   float* __restrict__ out) {
    int warp = blockIdx.x * 8 + (threadIdx.x >> 5);
    int n0 = warp * 32;
    if (n0 >= NN) return;
    int lane = threadIdx.x & 31;
    int c4 = lane * 4;
    float4 b = *(const float4*)&bias[c4];
    float4 acc = make_float4(0.f, 0.f, 0.f, 0.f);
    int gprev = __ldg(&batch_idx[n0]);
    int nend = (n0 + 32 < NN) ? n0 + 32 : NN;
    for (int n = n0; n < nend; n++) {
        int g = __ldg(&batch_idx[n]);
        if (g != gprev) {
            float w = __frcp_rn(fmaxf(g_cnt[gprev], 1.0f));
            redv4(&out[(size_t)gprev * HH + c4],
                  make_float4(acc.x * w, acc.y * w, acc.z * w, acc.w * w));
            acc = make_float4(0.f, 0.f, 0.f, 0.f);
            gprev = g;
        }
        float4 a = *(const float4*)&g_agg[(size_t)n * HH + c4];
        acc.x += fmaxf(a.x + b.x, 0.f);
        acc.y += fmaxf(a.y + b.y, 0.f);
        acc.z += fmaxf(a.z + b.z, 0.f);
        acc.w += fmaxf(a.w + b.w, 0.f);
    }
    float w = __frcp_rn(fmaxf(g_cnt[gprev], 1.0f));
    redv4(&out[(size_t)gprev * HH + c4],
          make_float4(acc.x * w, acc.y * w, acc.z * w, acc.w * w));
}

// ---------------- launch ------------------------------------------------------
extern "C" void kernel_launch(void* const* d_in, const int* in_sizes, int n_in,
                              void* d_out, int out_size) {
    const float* x         = (const float*)d_in[0];
    const int*   edge      = (const int*)d_in[1];     // [2, E]
    const int*   batch_idx = (const int*)d_in[2];
    const float* W1        = (const float*)d_in[3];
    const float* b1        = (const float*)d_in[4];
    const float* W2        = (const float*)d_in[5];
    const float* b2        = (const float*)d_in[6];
    const float* W3        = (const float*)d_in[7];
    const float* b3        = (const float*)d_in[8];
    float* out = (float*)d_out;

    const int* src = edge;
    const int* dst = edge + EE;

    float *hptr, *aggptr, *aggx;
    __nv_bfloat16 *w1h, *w1l, *w2h, *w2l, *w3h, *w3l;
    cudaGetSymbolAddress((void**)&hptr,   g_h);
    cudaGetSymbolAddress((void**)&aggptr, g_agg);
    cudaGetSymbolAddress((void**)&aggx,   g_aggx);
    cudaGetSymbolAddress((void**)&w1h, g_w1h);
    cudaGetSymbolAddress((void**)&w1l, g_w1l);
    cudaGetSymbolAddress((void**)&w2h, g_w2h);
    cudaGetSymbolAddress((void**)&w2l, g_w2l);
    cudaGetSymbolAddress((void**)&w3h, g_w3h);
    cudaGetSymbolAddress((void**)&w3l, g_w3l);

    const int SMEM_L1 = 4 * 128 * (32 + 8) * 2;   // 40960
    const int SMEM_L2 = 4 * 128 * (64 + 8) * 2;   // 73728
    cudaFuncSetAttribute(gemm_mma<32, 0, 0>,  cudaFuncAttributeMaxDynamicSharedMemorySize, SMEM_L1);
    cudaFuncSetAttribute(gemm_mma<128, 1, 1>, cudaFuncAttributeMaxDynamicSharedMemorySize, SMEM_L2);

    const int T = 256;
    const int gemm_grid = NPAD / 128;             // 1563
    const int half_grid = (EE / 4 + 15) / 16;     // 9375 (16 groups x 4 edges)
    const int scx_grid  = (EE / 2 + 31) / 32;     // 9375
    const int pool_grid = (NN / 32 + 7) / 8;      // 782

    init_kernel<<<(GG * HH + T - 1) / T, T>>>(out, W1, W2, W3);
    count_kernel<<<(EE + T - 1) / T, T>>>(dst, batch_idx);
    aggxinit_kernel<<<(NPAD * 8 + T - 1) / T, T>>>(x);
    scatterx_kernel<<<scx_grid, T>>>(x, src, dst);

    // layer 1: agg1 = (Â·X) @ W1  (no post-GEMM scatter)
    gemm_mma<32, 0, 0><<<gemm_grid, T, SMEM_L1>>>(aggx, nullptr, w1h, w1l, aggptr, nullptr);

    // layer 2
    gemm_mma<128, 1, 1><<<gemm_grid, T, SMEM_L2>>>(aggptr, b1, w2h, w2l, hptr, aggptr);
    scatter_half_kernel<0><<<half_grid, T>>>(src, dst);
    scatter_half_kernel<64><<<half_grid, T>>>(src, dst);

    // layer 3
    gemm_mma<128, 1, 1><<<gemm_grid, T, SMEM_L2>>>(aggptr, b2, w3h, w3l, hptr, aggptr);
    scatter_half_kernel<0><<<half_grid, T>>>(src, dst);
    scatter_half_kernel<64><<<half_grid, T>>>(src, dst);

    // final: run-batched relu + b3 + mean-pool
    pool_kernel<<<pool_grid, T>>>(b3, batch_idx, out);
}

// round 16
// speedup vs baseline: 1.4547x; 1.0398x over previous
#include <cuda_runtime.h>
#include <cuda_bf16.h>
#include <cstdint>

// Problem constants
#define NN 200000
#define NPAD 200064          // 1563 * 128
#define EE 600000
#define GG 8192
#define HH 128
#define DIN 30

typedef unsigned long long u64;
typedef unsigned int u32;

// ---------------- scratch (device globals; no allocations allowed) ----------
__device__ float g_aggx[(size_t)NPAD * 32];  // aggregated input (Â·X), K padded 32
__device__ __nv_bfloat16 g_w1h[128 * 32],  g_w1l[128 * 32];    // W1^T split
__device__ __nv_bfloat16 g_w2h[128 * 128], g_w2l[128 * 128];   // W2^T split
__device__ __nv_bfloat16 g_w3h[128 * 128], g_w3l[128 * 128];   // W3^T split
__device__ float g_h[(size_t)NPAD * HH];    // h = act @ W
__device__ float g_agg[(size_t)NPAD * HH];  // aggregation / pre-activation buffer
__device__ float g_deg[NN];                 // 1 + in-degree
__device__ float g_cnt[GG];                 // raw batch counts

// ---------------- helpers -----------------------------------------------------
__device__ __forceinline__ u32 smem_u32(const void* p) {
    u32 a;
    asm("{ .reg .u64 t; cvta.to.shared.u64 t, %1; cvt.u32.u64 %0, t; }" : "=r"(a) : "l"(p));
    return a;
}
__device__ __forceinline__ u32 pack2(__nv_bfloat16 a, __nv_bfloat16 b) {
    return (u32)__bfloat16_as_ushort(a) | ((u32)__bfloat16_as_ushort(b) << 16);
}
__device__ __forceinline__ void split8(const float* v, uint4& hi, uint4& lo) {
    __nv_bfloat16 h[8];
    float r[8];
#pragma unroll
    for (int i = 0; i < 8; i++) { h[i] = __float2bfloat16(v[i]); r[i] = v[i] - __bfloat162float(h[i]); }
    hi.x = pack2(h[0], h[1]); hi.y = pack2(h[2], h[3]);
    hi.z = pack2(h[4], h[5]); hi.w = pack2(h[6], h[7]);
    lo.x = pack2(__float2bfloat16(r[0]), __float2bfloat16(r[1]));
    lo.y = pack2(__float2bfloat16(r[2]), __float2bfloat16(r[3]));
    lo.z = pack2(__float2bfloat16(r[4]), __float2bfloat16(r[5]));
    lo.w = pack2(__float2bfloat16(r[6]), __float2bfloat16(r[7]));
}
__device__ __forceinline__ void mma16816(float* c, const u32* a, const u32* b) {
    asm volatile(
        "mma.sync.aligned.m16n8k16.row.col.f32.bf16.bf16.f32 "
        "{%0,%1,%2,%3}, {%4,%5,%6,%7}, {%8,%9}, {%0,%1,%2,%3};"
        : "+f"(c[0]), "+f"(c[1]), "+f"(c[2]), "+f"(c[3])
        : "r"(a[0]), "r"(a[1]), "r"(a[2]), "r"(a[3]), "r"(b[0]), "r"(b[1]));
}
__device__ __forceinline__ void ldsm4(u32* r, u32 addr) {
    asm volatile("ldmatrix.sync.aligned.m8n8.x4.shared.b16 {%0,%1,%2,%3}, [%4];"
                 : "=r"(r[0]), "=r"(r[1]), "=r"(r[2]), "=r"(r[3]) : "r"(addr));
}
__device__ __forceinline__ void redv4(float* p, float4 m) {
    asm volatile("red.global.add.v4.f32 [%0], {%1, %2, %3, %4};"
                 :: "l"(p), "f"(m.x), "f"(m.y), "f"(m.z), "f"(m.w)
                 : "memory");
}
__device__ __forceinline__ void cpasync16(u32 saddr, const void* gptr) {
    asm volatile("cp.async.cg.shared.global [%0], [%1], 16;"
                 :: "r"(saddr), "l"(gptr) : "memory");
}
#define CP_COMMIT() asm volatile("cp.async.commit_group;" ::: "memory")
#define CP_WAIT0()  asm volatile("cp.async.wait_group 0;" ::: "memory")

// ---------------- setup: zero out/deg/cnt + split all weights ----------------
__global__ void init_kernel(float* __restrict__ out,
                            const float* __restrict__ W1,
                            const float* __restrict__ W2,
                            const float* __restrict__ W3) {
    int idx = blockIdx.x * blockDim.x + threadIdx.x;
    if (idx < GG * HH) out[idx] = 0.0f;
    if (idx < NN) g_deg[idx] = 1.0f;           // self-loop
    if (idx < GG) g_cnt[idx] = 0.0f;
    if (idx < 128 * 32) {
        int c = idx >> 5, k = idx & 31;
        float v = (k < DIN) ? W1[(size_t)k * HH + c] : 0.0f;
        __nv_bfloat16 h = __float2bfloat16(v);
        g_w1h[idx] = h;
        g_w1l[idx] = __float2bfloat16(v - __bfloat162float(h));
    }
    if (idx < 128 * 128) {
        int c = idx >> 7, k = idx & 127;
        float v2 = W2[(size_t)k * HH + c];
        __nv_bfloat16 h2 = __float2bfloat16(v2);
        g_w2h[idx] = h2;
        g_w2l[idx] = __float2bfloat16(v2 - __bfloat162float(h2));
        float v3 = W3[(size_t)k * HH + c];
        __nv_bfloat16 h3 = __float2bfloat16(v3);
        g_w3h[idx] = h3;
        g_w3l[idx] = __float2bfloat16(v3 - __bfloat162float(h3));
    }
}

__global__ void count_kernel(const int* __restrict__ dst, const int* __restrict__ batch_idx) {
    int idx = blockIdx.x * blockDim.x + threadIdx.x;
    if (idx < EE) atomicAdd(&g_deg[dst[idx]], 1.0f);
    if (idx < NN) atomicAdd(&g_cnt[batch_idx[idx]], 1.0f);
}

// seed aggx with self-loop term x/deg (coalesced)
__global__ void aggxinit_kernel(const float* __restrict__ x) {
    int idx = blockIdx.x * blockDim.x + threadIdx.x;   // over NPAD*8
    if (idx >= NPAD * 8) return;
    int n = idx >> 3;
    int k = (idx & 7) * 4;
    float4 v = make_float4(0.f, 0.f, 0.f, 0.f);
    if (n < NN) {
        float d2 = __frcp_rn(g_deg[n]);
        if (k + 0 < DIN) v.x = x[(size_t)n * DIN + k + 0] * d2;
        if (k + 1 < DIN) v.y = x[(size_t)n * DIN + k + 1] * d2;
        if (k + 2 < DIN) v.z = x[(size_t)n * DIN + k + 2] * d2;
        if (k + 3 < DIN) v.w = x[(size_t)n * DIN + k + 3] * d2;
    }
    *(float4*)&g_aggx[(size_t)n * 32 + k] = v;
}

// 30-dim edge scatter on raw x, ILP-2 (unchanged from best)
__global__ void __launch_bounds__(256) scatterx_kernel(const float* __restrict__ x,
                                                       const int* __restrict__ src,
                                                       const int* __restrict__ dst) {
    int grp = blockIdx.x * 32 + (threadIdx.x >> 3);
    int e0 = grp * 2;
    if (e0 >= EE) return;
    int l = threadIdx.x & 7;
    int s0 = __ldg(&src[e0]),     d0 = __ldg(&dst[e0]);
    int s1 = __ldg(&src[e0 + 1]), d1 = __ldg(&dst[e0 + 1]);
    float w0 = rsqrtf(g_deg[s0] * g_deg[d0]);
    float w1 = rsqrtf(g_deg[s1] * g_deg[d1]);
    float v0[4], v1[4];
#pragma unroll
    for (int j = 0; j < 4; j++) {
        int k = l * 4 + j;
        v0[j] = (k < DIN) ? __ldg(&x[(size_t)s0 * DIN + k]) : 0.f;
        v1[j] = (k < DIN) ? __ldg(&x[(size_t)s1 * DIN + k]) : 0.f;
    }
    redv4(&g_aggx[(size_t)d0 * 32 + l * 4],
          make_float4(v0[0] * w0, v0[1] * w0, v0[2] * w0, v0[3] * w0));
    redv4(&g_aggx[(size_t)d1 * 32 + l * 4],
          make_float4(v1[0] * w1, v1[1] * w1, v1[2] * w1, v1[3] * w1));
}

// ---------------- layer-1 GEMM (K=32, single chunk; identical to best) ------
__global__ void __launch_bounds__(256) gemm_l1(
    const float* __restrict__ inf,
    const __nv_bfloat16* __restrict__ wh, const __nv_bfloat16* __restrict__ wl,
    float* __restrict__ hout)
{
    constexpr int KC = 32;
    constexpr u32 SPB = (KC + 8) * 2;     // 80
    constexpr u32 TILEB = 128 * SPB;
    constexpr int UNITS = 128 * (KC / 8);

    extern __shared__ char smem[];
    const u32 sb = smem_u32(smem);
    char* Ah = smem;
    char* Al = smem + TILEB;
    char* Whs = smem + 2 * TILEB;
    char* Wls = smem + 3 * TILEB;

    const int tid   = threadIdx.x;
    const int w     = tid >> 5;
    const int lane  = tid & 31;
    const int mrow  = (w & 3) * 32;
    const int ncol  = (w >> 2) * 64;
    const int node0 = blockIdx.x * 128;

    const u32 aAh = sb + (u32)(mrow + (lane & 15)) * SPB + (u32)((lane >> 4) * 16);
    const u32 bWh = sb + 2 * TILEB
                  + (u32)(ncol + (lane & 7) + ((lane >> 4) << 3)) * SPB
                  + (u32)(((lane >> 3) & 1) * 16);

    float acc[2][8][4];
#pragma unroll
    for (int mt = 0; mt < 2; mt++)
#pragma unroll
        for (int nt = 0; nt < 8; nt++)
#pragma unroll
            for (int i = 0; i < 4; i++) acc[mt][nt][i] = 0.f;

    for (int u = tid; u < UNITS; u += 256) {
        int row = u / (KC / 8);
        int cu  = u % (KC / 8);
        uint4 vh = *(const uint4*)&wh[(size_t)row * KC + cu * 8];
        uint4 vl = *(const uint4*)&wl[(size_t)row * KC + cu * 8];
        *(uint4*)(Whs + row * SPB + cu * 16) = vh;
        *(uint4*)(Wls + row * SPB + cu * 16) = vl;
    }
    for (int u = tid; u < UNITS; u += 256) {
        int row = u / (KC / 8);
        int cu  = u % (KC / 8);
        const float* s = inf + (size_t)(node0 + row) * KC + cu * 8;
        float4 a0 = *(const float4*)s;
        float4 a1 = *(const float4*)(s + 4);
        float v[8] = {a0.x, a0.y, a0.z, a0.w, a1.x, a1.y, a1.z, a1.w};
        uint4 vh, vl;
        split8(v, vh, vl);
        *(uint4*)(Ah + row * SPB + cu * 16) = vh;
        *(uint4*)(Al + row * SPB + cu * 16) = vl;
    }
    __syncthreads();

#pragma unroll
    for (int ks = 0; ks < KC / 16; ks++) {
        const u32 koff = (u32)(ks * 32);
        u32 ah0[4], ah1[4], al0[4], al1[4];
        ldsm4(ah0, aAh + koff);
        ldsm4(ah1, aAh + 16 * SPB + koff);
        ldsm4(al0, aAh + TILEB + koff);
        ldsm4(al1, aAh + TILEB + 16 * SPB + koff);
#pragma unroll
        for (int np = 0; np < 4; np++) {
            const u32 bo = (u32)(np * 16) * SPB + koff;
            u32 bh4[4], bl4[4];
            ldsm4(bh4, bWh + bo);
            ldsm4(bl4, bWh + TILEB + bo);
            const int nt0 = np * 2, nt1 = np * 2 + 1;
            mma16816(acc[0][nt0], ah0, bh4);
            mma16816(acc[1][nt0], ah1, bh4);
            mma16816(acc[0][nt1], ah0, bh4 + 2);
            mma16816(acc[1][nt1], ah1, bh4 + 2);
            mma16816(acc[0][nt0], ah0, bl4);
            mma16816(acc[1][nt0], ah1, bl4);
            mma16816(acc[0][nt1], ah0, bl4 + 2);
            mma16816(acc[1][nt1], ah1, bl4 + 2);
            mma16816(acc[0][nt0], al0, bh4);
            mma16816(acc[1][nt0], al1, bh4);
            mma16816(acc[0][nt1], al0, bh4 + 2);
            mma16816(acc[1][nt1], al1, bh4 + 2);
        }
    }

#pragma unroll
    for (int mt = 0; mt < 2; mt++) {
        int r0 = node0 + mrow + mt * 16 + (lane >> 2);
        int r1 = r0 + 8;
#pragma unroll
        for (int nt = 0; nt < 8; nt++) {
            int cc = ncol + nt * 8 + (lane & 3) * 2;
            *(float2*)&hout[(size_t)r0 * HH + cc] = make_float2(acc[mt][nt][0], acc[mt][nt][1]);
            *(float2*)&hout[(size_t)r1 * HH + cc] = make_float2(acc[mt][nt][2], acc[mt][nt][3]);
        }
    }
}

// ---------------- fused GEMM (K=128), cp.async-pipelined A staging ----------
// Raw fp32 A chunk [128 x 64] prefetched into smem via cp.async, overlapped
// with the previous chunk's MMA. Transform (relu+bias+split) runs from smem.
__global__ void __launch_bounds__(256) gemm_fused_pipe(
    const float* __restrict__ inf, const float* __restrict__ bias,
    const __nv_bfloat16* __restrict__ wh, const __nv_bfloat16* __restrict__ wl,
    float* __restrict__ hout, float* __restrict__ agg)
{
    constexpr int KT = 128;
    constexpr int KC = 64;
    constexpr u32 SPB = (KC + 8) * 2;     // 144
    constexpr u32 TILEB = 128 * SPB;      // 18432
    constexpr int UNITS = 128 * (KC / 8); // 1024
    constexpr u32 RAWOFF = 4 * TILEB;     // 73728
    // raw chunk: 128 rows x 64 fp32 = 32768 B; 16B segments: 2048

    extern __shared__ char smem[];
    const u32 sb = smem_u32(smem);
    char* Ah = smem;
    char* Al = smem + TILEB;
    char* Whs = smem + 2 * TILEB;
    char* Wls = smem + 3 * TILEB;
    const float* rawf = (const float*)(smem + RAWOFF);

    const int tid   = threadIdx.x;
    const int w     = tid >> 5;
    const int lane  = tid & 31;
    const int mrow  = (w & 3) * 32;
    const int ncol  = (w >> 2) * 64;
    const int node0 = blockIdx.x * 128;

    const u32 aAh = sb + (u32)(mrow + (lane & 15)) * SPB + (u32)((lane >> 4) * 16);
    const u32 bWh = sb + 2 * TILEB
                  + (u32)(ncol + (lane & 7) + ((lane >> 4) << 3)) * SPB
                  + (u32)(((lane >> 3) & 1) * 16);

    float acc[2][8][4];
#pragma unroll
    for (int mt = 0; mt < 2; mt++)
#pragma unroll
        for (int nt = 0; nt < 8; nt++)
#pragma unroll
            for (int i = 0; i < 4; i++) acc[mt][nt][i] = 0.f;

    // prefetch raw A chunk 0
#pragma unroll
    for (int i = 0; i < 8; i++) {
        int seg = tid + 256 * i;              // 0..2047
        int row = seg >> 4;
        int s4  = seg & 15;                   // 16B segment within row
        cpasync16(sb + RAWOFF + (u32)seg * 16,
                  inf + (size_t)(node0 + row) * KT + 0 + s4 * 4);
    }
    CP_COMMIT();

#pragma unroll
    for (int c = 0; c < KT / KC; c++) {
        const int k0 = c * KC;
        CP_WAIT0();
        __syncthreads();   // raw chunk c landed; previous chunk's MMA done (tiles free)

        // stage W chunk c (L2-hot)
        for (int u = tid; u < UNITS; u += 256) {
            int row = u / (KC / 8);
            int cu  = u % (KC / 8);
            uint4 vh = *(const uint4*)&wh[(size_t)row * KT + k0 + cu * 8];
            uint4 vl = *(const uint4*)&wl[(size_t)row * KT + k0 + cu * 8];
            *(uint4*)(Whs + row * SPB + cu * 16) = vh;
            *(uint4*)(Wls + row * SPB + cu * 16) = vl;
        }
        // transform raw smem chunk -> Ah/Al tiles (relu+bias+split)
        for (int u = tid; u < UNITS; u += 256) {
            int row = u / (KC / 8);
            int cu  = u % (KC / 8);
            const float* s = rawf + row * KC + cu * 8;
            float4 a0 = *(const float4*)s;
            float4 a1 = *(const float4*)(s + 4);
            float4 b0 = *(const float4*)&bias[k0 + cu * 8];
            float4 b1 = *(const float4*)&bias[k0 + cu * 8 + 4];
            float v[8];
            v[0] = fmaxf(a0.x + b0.x, 0.f); v[1] = fmaxf(a0.y + b0.y, 0.f);
            v[2] = fmaxf(a0.z + b0.z, 0.f); v[3] = fmaxf(a0.w + b0.w, 0.f);
            v[4] = fmaxf(a1.x + b1.x, 0.f); v[5] = fmaxf(a1.y + b1.y, 0.f);
            v[6] = fmaxf(a1.z + b1.z, 0.f); v[7] = fmaxf(a1.w + b1.w, 0.f);
            uint4 vh, vl;
            split8(v, vh, vl);
            *(uint4*)(Ah + row * SPB + cu * 16) = vh;
            *(uint4*)(Al + row * SPB + cu * 16) = vl;
        }
        __syncthreads();   // tiles ready; rawbuf fully consumed

        // prefetch raw A chunk c+1 (overlaps with MMA below)
        if (c + 1 < KT / KC) {
            const int k1 = (c + 1) * KC;
#pragma unroll
            for (int i = 0; i < 8; i++) {
                int seg = tid + 256 * i;
                int row = seg >> 4;
                int s4  = seg & 15;
                cpasync16(sb + RAWOFF + (u32)seg * 16,
                          inf + (size_t)(node0 + row) * KT + k1 + s4 * 4);
            }
            CP_COMMIT();
        }

        // MMA over chunk c
#pragma unroll
        for (int ks = 0; ks < KC / 16; ks++) {
            const u32 koff = (u32)(ks * 32);
            u32 ah0[4], ah1[4], al0[4], al1[4];
            ldsm4(ah0, aAh + koff);
            ldsm4(ah1, aAh + 16 * SPB + koff);
            ldsm4(al0, aAh + TILEB + koff);
            ldsm4(al1, aAh + TILEB + 16 * SPB + koff);
#pragma unroll
            for (int np = 0; np < 4; np++) {
                const u32 bo = (u32)(np * 16) * SPB + koff;
                u32 bh4[4], bl4[4];
                ldsm4(bh4, bWh + bo);
                ldsm4(bl4, bWh + TILEB + bo);
                const int nt0 = np * 2, nt1 = np * 2 + 1;
                mma16816(acc[0][nt0], ah0, bh4);
                mma16816(acc[1][nt0], ah1, bh4);
                mma16816(acc[0][nt1], ah0, bh4 + 2);
                mma16816(acc[1][nt1], ah1, bh4 + 2);
                mma16816(acc[0][nt0], ah0, bl4);
                mma16816(acc[1][nt0], ah1, bl4);
                mma16816(acc[0][nt1], ah0, bl4 + 2);
                mma16816(acc[1][nt1], ah1, bl4 + 2);
                mma16816(acc[0][nt0], al0, bh4);
                mma16816(acc[1][nt0], al1, bh4);
                mma16816(acc[0][nt1], al0, bh4 + 2);
                mma16816(acc[1][nt1], al1, bh4 + 2);
            }
        }
    }

    // ---- epilogue: write h and agg-seed (h/deg)
#pragma unroll
    for (int mt = 0; mt < 2; mt++) {
        int r0 = node0 + mrow + mt * 16 + (lane >> 2);
        int r1 = r0 + 8;
        float d20 = 0.f, d21 = 0.f;
        if (r0 < NN) d20 = __frcp_rn(g_deg[r0]);
        if (r1 < NN) d21 = __frcp_rn(g_deg[r1]);
#pragma unroll
        for (int nt = 0; nt < 8; nt++) {
            int cc = ncol + nt * 8 + (lane & 3) * 2;
            float2 h0 = make_float2(acc[mt][nt][0], acc[mt][nt][1]);
            float2 h1 = make_float2(acc[mt][nt][2], acc[mt][nt][3]);
            *(float2*)&hout[(size_t)r0 * HH + cc] = h0;
            *(float2*)&hout[(size_t)r1 * HH + cc] = h1;
            *(float2*)&agg[(size_t)r0 * HH + cc] = make_float2(h0.x * d20, h0.y * d20);
            *(float2*)&agg[(size_t)r1 * HH + cc] = make_float2(h1.x * d21, h1.y * d21);
        }
    }
}

// ---------------- 128-dim scatter, TWO-PASS over feature halves -------------
template <int C0>
__global__ void __launch_bounds__(256) scatter_half_kernel(const int* __restrict__ src,
                                                           const int* __restrict__ dst) {
    int grp = blockIdx.x * 16 + (threadIdx.x >> 4);
    int e0 = grp * 4;
    if (e0 >= EE) return;              // EE % 4 == 0
    int l = threadIdx.x & 15;
    int s[4], d[4];
#pragma unroll
    for (int i = 0; i < 4; i++) {
        s[i] = __ldg(&src[e0 + i]);
        d[i] = __ldg(&dst[e0 + i]);
    }
    float wt[4];
#pragma unroll
    for (int i = 0; i < 4; i++)
        wt[i] = rsqrtf(g_deg[s[i]] * g_deg[d[i]]);
    float4 v[4];
#pragma unroll
    for (int i = 0; i < 4; i++)
        v[i] = *(const float4*)&g_h[(size_t)s[i] * HH + C0 + l * 4];
#pragma unroll
    for (int i = 0; i < 4; i++)
        redv4(&g_agg[(size_t)d[i] * HH + C0 + l * 4],
              make_float4(v[i].x * wt[i], v[i].y * wt[i], v[i].z * wt[i], v[i].w * wt[i]));
}

// ---------------- final pool: run-batched over sorted batch_idx -------------
__global__ void __launch_bounds__(256) pool_kernel(const float* __restrict__ bias,
                                                   const int* __restrict__ batch_idx,
                                                   float* __restrict__ out) {
    int warp = blockIdx.x * 8 + (threadIdx.x >> 5);
    int n0 = warp * 32;
    if (n0 >= NN) return;
    int lane = threadIdx.x & 31;
    int c4 = lane * 4;
    float4 b = *(const float4*)&bias[c4];
    float4 acc = make_float4(0.f, 0.f, 0.f, 0.f);
    int gprev = __ldg(&batch_idx[n0]);
    int nend = (n0 + 32 < NN) ? n0 + 32 : NN;
    for (int n = n0; n < nend; n++) {
        int g = __ldg(&batch_idx[n]);
        if (g != gprev) {
            float w = __frcp_rn(fmaxf(g_cnt[gprev], 1.0f));
            redv4(&out[(size_t)gprev * HH + c4],
                  make_float4(acc.x * w, acc.y * w, acc.z * w, acc.w * w));
            acc = make_float4(0.f, 0.f, 0.f, 0.f);
            gprev = g;
        }
        float4 a = *(const float4*)&g_agg[(size_t)n * HH + c4];
        acc.x += fmaxf(a.x + b.x, 0.f);
        acc.y += fmaxf(a.y + b.y, 0.f);
        acc.z += fmaxf(a.z + b.z, 0.f);
        acc.w += fmaxf(a.w + b.w, 0.f);
    }
    float w = __frcp_rn(fmaxf(g_cnt[gprev], 1.0f));
    redv4(&out[(size_t)gprev * HH + c4],
          make_float4(acc.x * w, acc.y * w, acc.z * w, acc.w * w));
}

// ---------------- launch ------------------------------------------------------
extern "C" void kernel_launch(void* const* d_in, const int* in_sizes, int n_in,
                              void* d_out, int out_size) {
    const float* x         = (const float*)d_in[0];
    const int*   edge      = (const int*)d_in[1];     // [2, E]
    const int*   batch_idx = (const int*)d_in[2];
    const float* W1        = (const float*)d_in[3];
    const float* b1        = (const float*)d_in[4];
    const float* W2        = (const float*)d_in[5];
    const float* b2        = (const float*)d_in[6];
    const float* W3        = (const float*)d_in[7];
    const float* b3        = (const float*)d_in[8];
    float* out = (float*)d_out;

    const int* src = edge;
    const int* dst = edge + EE;

    float *hptr, *aggptr, *aggx;
    __nv_bfloat16 *w1h, *w1l, *w2h, *w2l, *w3h, *w3l;
    cudaGetSymbolAddress((void**)&hptr,   g_h);
    cudaGetSymbolAddress((void**)&aggptr, g_agg);
    cudaGetSymbolAddress((void**)&aggx,   g_aggx);
    cudaGetSymbolAddress((void**)&w1h, g_w1h);
    cudaGetSymbolAddress((void**)&w1l, g_w1l);
    cudaGetSymbolAddress((void**)&w2h, g_w2h);
    cudaGetSymbolAddress((void**)&w2l, g_w2l);
    cudaGetSymbolAddress((void**)&w3h, g_w3h);
    cudaGetSymbolAddress((void**)&w3l, g_w3l);

    const int SMEM_L1 = 4 * 128 * (32 + 8) * 2;             // 40960
    const int SMEM_LP = 4 * 128 * (64 + 8) * 2 + 32768;     // 106496
    cudaFuncSetAttribute(gemm_l1,         cudaFuncAttributeMaxDynamicSharedMemorySize, SMEM_L1);
    cudaFuncSetAttribute(gemm_fused_pipe, cudaFuncAttributeMaxDynamicSharedMemorySize, SMEM_LP);

    const int T = 256;
    const int gemm_grid = NPAD / 128;             // 1563
    const int half_grid = (EE / 4 + 15) / 16;     // 9375
    const int scx_grid  = (EE / 2 + 31) / 32;     // 9375
    const int pool_grid = (NN / 32 + 7) / 8;      // 782

    init_kernel<<<(GG * HH + T - 1) / T, T>>>(out, W1, W2, W3);
    count_kernel<<<(EE + T - 1) / T, T>>>(dst, batch_idx);
    aggxinit_kernel<<<(NPAD * 8 + T - 1) / T, T>>>(x);
    scatterx_kernel<<<scx_grid, T>>>(x, src, dst);

    // layer 1: agg1 = (Â·X) @ W1  (no post-GEMM scatter)
    gemm_l1<<<gemm_grid, T, SMEM_L1>>>(aggx, w1h, w1l, aggptr);

    // layer 2
    gemm_fused_pipe<<<gemm_grid, T, SMEM_LP>>>(aggptr, b1, w2h, w2l, hptr, aggptr);
    scatter_half_kernel<0><<<half_grid, T>>>(src, dst);
    scatter_half_kernel<64><<<half_grid, T>>>(src, dst);

    // layer 3
    gemm_fused_pipe<<<gemm_grid, T, SMEM_LP>>>(aggptr, b2, w3h, w3l, hptr, aggptr);
    scatter_half_kernel<0><<<half_grid, T>>>(src, dst);
    scatter_half_kernel<64><<<half_grid, T>>>(src, dst);

    // final: run-batched relu + b3 + mean-pool
    pool_kernel<<<pool_grid, T>>>(b3, batch_idx, out);
}